// round 16
// baseline (speedup 1.0000x reference)
#include <cuda_runtime.h>
#include <cuda_bf16.h>
#include <cuda_fp16.h>
#include <math.h>
#include <stdint.h>

// Problem constants
#define BB 2
#define SS 2048
#define DM 2048
#define NH 32
#define NKV 8
#define HD 64
#define MTOT (BB * SS)          // 4096
#define QDIM (NH * HD)          // 2048
#define KVDIM (NKV * HD)        // 512
#define QKVD (QDIM + 2 * KVDIM) // 3072

// scale/log2 fold: (1/sqrt(64)) * log2(e)
#define QSCALE 0.18033688011112042f

// ---------------------------------------------------------------------------
// Scratch (device globals)
// ---------------------------------------------------------------------------
__device__ __half g_xf[MTOT * DM];              // x fp16
__device__ __half g_Wc[QKVD * DM];              // [wq;wk;wv] fp16
__device__ __half g_Wof[DM * QDIM];             // wo fp16
// per-head attention operands [b][h][s][64]
__device__ __half g_Qf[BB * NH * SS * HD];      // fp16, QSCALE folded
__device__ __half g_Kf[BB * NKV * SS * HD];     // fp16
__device__ __half g_Vf[BB * NKV * SS * HD];     // fp16
// attention output fp16, [b][s][2048] (GEMM-ready)
__device__ __half g_Of[MTOT * QDIM];

// ---------------------------------------------------------------------------
// PTX helpers
// ---------------------------------------------------------------------------
__device__ __forceinline__ uint32_t smem_u32(const void* p) {
    uint32_t a;
    asm("{ .reg .u64 t; cvta.to.shared.u64 t, %1; cvt.u32.u64 %0, t; }" : "=r"(a) : "l"(p));
    return a;
}
__device__ __forceinline__ void ldsm4(uint32_t* r, uint32_t addr) {
    asm volatile("ldmatrix.sync.aligned.m8n8.x4.shared.b16 {%0,%1,%2,%3}, [%4];"
                 : "=r"(r[0]), "=r"(r[1]), "=r"(r[2]), "=r"(r[3]) : "r"(addr));
}
__device__ __forceinline__ void ldsm4t(uint32_t* r, uint32_t addr) {
    asm volatile("ldmatrix.sync.aligned.m8n8.x4.trans.shared.b16 {%0,%1,%2,%3}, [%4];"
                 : "=r"(r[0]), "=r"(r[1]), "=r"(r[2]), "=r"(r[3]) : "r"(addr));
}
__device__ __forceinline__ void ldsm2t(uint32_t* r, uint32_t addr) {
    asm volatile("ldmatrix.sync.aligned.m8n8.x2.trans.shared.b16 {%0,%1}, [%2];"
                 : "=r"(r[0]), "=r"(r[1]) : "r"(addr));
}
__device__ __forceinline__ void mma16816h(float* c, const uint32_t* a, const uint32_t* b) {
    asm volatile(
        "mma.sync.aligned.m16n8k16.row.col.f32.f16.f16.f32 "
        "{%0,%1,%2,%3}, {%4,%5,%6,%7}, {%8,%9}, {%0,%1,%2,%3};"
        : "+f"(c[0]), "+f"(c[1]), "+f"(c[2]), "+f"(c[3])
        : "r"(a[0]), "r"(a[1]), "r"(a[2]), "r"(a[3]), "r"(b[0]), "r"(b[1]));
}
__device__ __forceinline__ void cp_async16(uint32_t saddr, const void* gaddr) {
    asm volatile("cp.async.cg.shared.global [%0], [%1], 16;" :: "r"(saddr), "l"(gaddr));
}
__device__ __forceinline__ float ex2f(float x) {
    float y;
    asm("ex2.approx.ftz.f32 %0, %1;" : "=f"(y) : "f"(x));
    return y;
}
__device__ __forceinline__ uint32_t pack_f16x2(float lo, float hi) {
    uint32_t d;
    asm("cvt.rn.f16x2.f32 %0, %1, %2;" : "=r"(d) : "f"(hi), "f"(lo));
    return d;
}
__device__ __forceinline__ uint32_t ex2_f16x2(uint32_t x) {
    uint32_t y;
    asm("ex2.approx.f16x2 %0, %1;" : "=r"(y) : "r"(x));
    return y;
}

// ---------------------------------------------------------------------------
// fp16 1-term GEMM: C = A[M,K] * B[NN,K]^T  (fp32 acc)
// CTA tile 256x128, BK=32, 512 threads (16 warps, warp tile 32x64, 8m x 2n),
// 3-stage cp.async. MODE 0: fp32 C. MODE 1: fused RoPE + per-head relayout.
// ---------------------------------------------------------------------------
#define GA_ARR 20480                   // 256 rows * 80 B
#define GB_ARR 10240                   // 128 rows * 80 B
#define G_STAGE (GA_ARR + GB_ARR)      // 30720
#define G_SMEM_TOTAL (3 * G_STAGE)     // 92160

template <int MODE>
__global__ __launch_bounds__(512, 1) void gemm2(
    const __half* __restrict__ A, const __half* __restrict__ B,
    float* __restrict__ C, int NN, int K,
    const float* __restrict__ cosT, const float* __restrict__ sinT,
    __half* __restrict__ Qf, __half* __restrict__ Kf, __half* __restrict__ Vf)
{
    extern __shared__ char smem[];
    const uint32_t sb = smem_u32(smem);
    const int tid = threadIdx.x;
    const int wid = tid >> 5;
    const int lane = tid & 31;
    const int wm = wid & 7;          // 0..7 -> 32 rows each
    const int wn = wid >> 3;         // 0..1 -> 64 cols each
    const int m0 = blockIdx.y * 256;
    const int n0 = blockIdx.x * 128;

    const __half* const Ap = A + (size_t)m0 * K;
    const __half* const Bp = B + (size_t)n0 * K;

    float acc[2][8][4];
#pragma unroll
    for (int i = 0; i < 2; i++)
#pragma unroll
        for (int j = 0; j < 8; j++)
#pragma unroll
            for (int q = 0; q < 4; q++) acc[i][j][q] = 0.0f;

    const int NC = K / 32;
    const int lg = lane >> 3;
    const int lr = lane & 7;

#define LOADSTAGE(cc) do {                                                     \
    const uint32_t stg = ((cc) % 3) * G_STAGE;                                 \
    const int k0 = (cc) * 32;                                                  \
    _Pragma("unroll")                                                          \
    for (int i = 0; i < 3; i++) {                                              \
        int gidx = tid + i * 512;       /* 0..1535 */                          \
        if (gidx < 1024) {              /* A: 256 rows x 4 chunks */           \
            int row = gidx >> 2;                                               \
            int q = gidx & 3;                                                  \
            cp_async16(sb + stg + row * 80 + q * 16,                           \
                       Ap + (size_t)row * K + k0 + q * 8);                     \
        } else {                        /* B: 128 rows x 4 chunks */           \
            int w = gidx - 1024;                                               \
            int row = w >> 2;                                                  \
            int q = w & 3;                                                     \
            cp_async16(sb + stg + GA_ARR + row * 80 + q * 16,                  \
                       Bp + (size_t)row * K + k0 + q * 8);                     \
        }                                                                      \
    }                                                                          \
    asm volatile("cp.async.commit_group;" ::: "memory");                       \
} while (0)

    LOADSTAGE(0);
    LOADSTAGE(1);

    for (int c = 0; c < NC; c++) {
        if (c + 1 < NC) { asm volatile("cp.async.wait_group 1;" ::: "memory"); }
        else            { asm volatile("cp.async.wait_group 0;" ::: "memory"); }
        __syncthreads();
        if (c + 2 < NC) LOADSTAGE(c + 2);

        const uint32_t stg = sb + (c % 3) * G_STAGE;
        const uint32_t sA = stg;
        const uint32_t sB = stg + GA_ARR;

#pragma unroll
        for (int kk = 0; kk < 2; kk++) {
            const int kbyte = kk * 32;
            uint32_t fA[2][4];
#pragma unroll
            for (int mt = 0; mt < 2; mt++) {
                int arow = wm * 32 + mt * 16 + (lg & 1) * 8 + lr;
                uint32_t aoff = (uint32_t)(arow * 80 + kbyte + (lg >> 1) * 16);
                ldsm4(fA[mt], sA + aoff);
            }
#pragma unroll
            for (int np = 0; np < 4; np++) {
                int brow = wn * 64 + np * 16 + (lg >> 1) * 8 + lr;
                uint32_t boff = (uint32_t)(brow * 80 + kbyte + (lg & 1) * 16);
                uint32_t fB[4];
                ldsm4(fB, sB + boff);
#pragma unroll
                for (int mt = 0; mt < 2; mt++) {
                    mma16816h(acc[mt][np * 2], fA[mt], fB);
                    mma16816h(acc[mt][np * 2 + 1], fA[mt], fB + 2);
                }
            }
        }
    }

    if (MODE == 0) {
#pragma unroll
        for (int mt = 0; mt < 2; mt++) {
            int row0 = m0 + wm * 32 + mt * 16 + (lane >> 2);
#pragma unroll
            for (int nt = 0; nt < 8; nt++) {
                int col = n0 + wn * 64 + nt * 8 + (lane & 3) * 2;
                float2 v0 = {acc[mt][nt][0], acc[mt][nt][1]};
                float2 v1 = {acc[mt][nt][2], acc[mt][nt][3]};
                *(float2*)(C + (size_t)row0 * NN + col) = v0;
                *(float2*)(C + (size_t)(row0 + 8) * NN + col) = v1;
            }
        }
    } else {
        // Fused QKV epilogue. Warp's 64-col tile = exactly one head.
        const int col0 = n0 + wn * 64;
#pragma unroll
        for (int mt = 0; mt < 2; mt++) {
#pragma unroll
            for (int rr = 0; rr < 2; rr++) {
                int row = m0 + wm * 32 + mt * 16 + (lane >> 2) + rr * 8;
                int s = row & (SS - 1);
                int b = row >> 11;
                if (col0 < QDIM + KVDIM) {
                    bool isQ = col0 < QDIM;
                    __half* dst;
                    if (isQ) {
                        int h = col0 >> 6;
                        dst = Qf + ((size_t)(b * NH + h) * SS + s) * 64;
                    } else {
                        int kvh = (col0 - QDIM) >> 6;
                        dst = Kf + ((size_t)(b * NKV + kvh) * SS + s) * 64;
                    }
                    float sc = isQ ? QSCALE : 1.0f;
#pragma unroll
                    for (int nt = 0; nt < 4; nt++) {
                        int d = nt * 8 + (lane & 3) * 2;
                        float a0 = acc[mt][nt][rr * 2], a1 = acc[mt][nt][rr * 2 + 1];
                        float b0 = acc[mt][nt + 4][rr * 2], b1 = acc[mt][nt + 4][rr * 2 + 1];
                        int ci = s * 32 + (d >> 1);
                        float c1 = cosT[ci], s1 = sinT[ci];
                        float c2 = cosT[ci + 16], s2 = sinT[ci + 16];
                        __half2 lo2 = __floats2half2_rn((a0 * c1 - b0 * s1) * sc,
                                                        (a1 * c1 - b1 * s1) * sc);
                        __half2 hi2 = __floats2half2_rn((b0 * c2 + a0 * s2) * sc,
                                                        (b1 * c2 + a1 * s2) * sc);
                        *(__half2*)(dst + d) = lo2;
                        *(__half2*)(dst + d + 32) = hi2;
                    }
                } else {
                    int kvh = (col0 - QDIM - KVDIM) >> 6;
                    __half* dst = Vf + ((size_t)(b * NKV + kvh) * SS + s) * 64;
#pragma unroll
                    for (int nt = 0; nt < 8; nt++) {
                        int d = nt * 8 + (lane & 3) * 2;
                        *(__half2*)(dst + d) =
                            __floats2half2_rn(acc[mt][nt][rr * 2], acc[mt][nt][rr * 2 + 1]);
                    }
                }
            }
        }
    }
#undef LOADSTAGE
}

// ---------------------------------------------------------------------------
// cvt_all: x, [wq;wk;wv], wo -> fp16
// ---------------------------------------------------------------------------
#define CV_NX (MTOT * DM / 2)
#define CV_NQ (QDIM * DM / 2)
#define CV_NK (KVDIM * DM / 2)
#define CV_NO (DM * QDIM / 2)
#define CV_TOTAL (CV_NX + CV_NQ + 2 * CV_NK + CV_NO)

__global__ void cvt_all(const float* __restrict__ x, const float* __restrict__ wq,
                        const float* __restrict__ wk, const float* __restrict__ wv,
                        const float* __restrict__ wo,
                        __half* __restrict__ xf, __half* __restrict__ Wc,
                        __half* __restrict__ Wof) {
    int i = blockIdx.x * blockDim.x + threadIdx.x;
    const float* src;
    __half* dst;
    int off;
    if (i < CV_NX) { src = x; dst = xf; off = i; }
    else if (i < CV_NX + CV_NQ) { src = wq; dst = Wc; off = i - CV_NX; }
    else if (i < CV_NX + CV_NQ + CV_NK) {
        src = wk; dst = Wc + (size_t)QDIM * DM; off = i - CV_NX - CV_NQ;
    } else if (i < CV_NX + CV_NQ + 2 * CV_NK) {
        src = wv; dst = Wc + (size_t)(QDIM + KVDIM) * DM; off = i - CV_NX - CV_NQ - CV_NK;
    } else if (i < CV_TOTAL) {
        src = wo; dst = Wof; off = i - CV_NX - CV_NQ - 2 * CV_NK;
    } else return;
    float2 v = ((const float2*)src)[off];
    ((__half2*)dst)[off] = __floats2half2_rn(v.x, v.y);
}

// ---------------------------------------------------------------------------
// MMA flash attention v4 (validated R15): fp16 QxK (1 MMA), fp16 PxV (1 MMA),
// ones-column row sums. LPT: qb processed in descending order.
// grid (S/128, NH, BB), 256 threads.
// ---------------------------------------------------------------------------
#define FSTRB 144
#define FQ_BYTES (128 * FSTRB)
#define FARR (64 * FSTRB)
#define FKV0 FQ_BYTES
#define FSTAGE (2 * FARR)            // 18432
#define FL_SMEM (FKV0 + 2 * FSTAGE)  // 55296

__global__ __launch_bounds__(256, 1) void flash_mma(
    const __half* __restrict__ Qf, const __half* __restrict__ Kf,
    const __half* __restrict__ Vf, __half* __restrict__ Of)
{
    extern __shared__ char sm[];
    const uint32_t sb = smem_u32(sm);
    const int tid = threadIdx.x;
    const int lane = tid & 31;
    const int wm = tid >> 5;
    const int qb = (gridDim.x - 1) - blockIdx.x;   // LPT: big tiles first
    const int h = blockIdx.y;
    const int b = blockIdx.z;
    const int kvh = h >> 2;
    const int nkt = 2 * (qb + 1);

    const size_t qg = ((size_t)(b * NH + h) * SS + qb * 128) * 64;
    const size_t kg = ((size_t)(b * NKV + kvh) * SS) * 64;

    {
#pragma unroll
        for (int i = 0; i < 4; i++) {
            int g = tid + i * 256;
            int row = g >> 3;
            int ch = g & 7;
            cp_async16(sb + row * FSTRB + ch * 16, Qf + qg + (size_t)row * 64 + ch * 8);
        }
        asm volatile("cp.async.commit_group;" ::: "memory");
    }

#define LOADKV(kt_) do {                                                        \
    int j0_ = (kt_) * 64;                                                       \
    uint32_t stg_ = sb + FKV0 + ((kt_) & 1) * FSTAGE;                           \
    const char* karr[2] = {                                                     \
        (const char*)(Kf + kg + (size_t)j0_ * 64),                              \
        (const char*)(Vf + kg + (size_t)j0_ * 64)};                             \
    _Pragma("unroll")                                                           \
    for (int i = 0; i < 4; i++) {                                               \
        int g = tid + i * 256;                                                  \
        int arr = g >> 9;                                                       \
        int w = g & 511;                                                        \
        int row = w >> 3;                                                       \
        int ch = w & 7;                                                         \
        cp_async16(stg_ + arr * FARR + row * FSTRB + ch * 16,                   \
                   karr[arr] + row * 128 + ch * 16);                            \
    }                                                                           \
    asm volatile("cp.async.commit_group;" ::: "memory");                        \
} while (0)

    LOADKV(0);
    if (nkt > 1) LOADKV(1);

    if (tid < 128) {
        int stage = tid >> 6;
        int row = tid & 63;
        uint32_t off = FKV0 + stage * FSTAGE + FARR + row * FSTRB + 128;
        uint4 ones = {0x00003C00u, 0u, 0u, 0u};
        *(uint4*)(sm + off) = ones;
    }

    if (nkt > 1) { asm volatile("cp.async.wait_group 1;" ::: "memory"); }
    else         { asm volatile("cp.async.wait_group 0;" ::: "memory"); }
    __syncthreads();

    uint32_t qf[4][4];
#pragma unroll
    for (int kk = 0; kk < 4; kk++) {
        uint32_t addr = sb + (uint32_t)((wm * 16 + (lane & 15)) * FSTRB
                                        + kk * 32 + (lane >> 4) * 16);
        ldsm4(qf[kk], addr);
    }

    float co[8][4];
#pragma unroll
    for (int i = 0; i < 8; i++)
#pragma unroll
        for (int j = 0; j < 4; j++) co[i][j] = 0.0f;
    float lacc[4] = {0.0f, 0.0f, 0.0f, 0.0f};
    float m0 = -1e30f, m1 = -1e30f;

    const int lg = lane >> 3;
    const int lr = lane & 7;
    const int qr0 = qb * 128 + wm * 16 + (lane >> 2);

    for (int kt = 0; kt < nkt; kt++) {
        if (kt > 0) {
            if (kt + 1 < nkt) { asm volatile("cp.async.wait_group 1;" ::: "memory"); }
            else              { asm volatile("cp.async.wait_group 0;" ::: "memory"); }
            __syncthreads();
        }
        const uint32_t sKf = sb + FKV0 + (kt & 1) * FSTAGE;
        const uint32_t sVf = sKf + FARR;

        float cs[8][4];
#pragma unroll
        for (int i = 0; i < 8; i++)
#pragma unroll
            for (int j = 0; j < 4; j++) cs[i][j] = 0.0f;

#pragma unroll
        for (int kk = 0; kk < 4; kk++) {
#pragma unroll
            for (int ng = 0; ng < 4; ng++) {
                uint32_t boff = (uint32_t)((ng * 16 + (lg >> 1) * 8 + lr) * FSTRB
                                           + kk * 32 + (lg & 1) * 16);
                uint32_t bk[4];
                ldsm4(bk, sKf + boff);
                mma16816h(cs[ng * 2], qf[kk], bk);
                mma16816h(cs[ng * 2 + 1], qf[kk], bk + 2);
            }
        }

        if (kt >= nkt - 2) {
            int gcol0 = kt * 64 + (lane & 3) * 2;
#pragma unroll
            for (int n = 0; n < 8; n++) {
#pragma unroll
                for (int t = 0; t < 2; t++) {
                    int col = gcol0 + n * 8 + t;
                    if (col > qr0) cs[n][t] = -1e30f;
                    if (col > qr0 + 8) cs[n][t + 2] = -1e30f;
                }
            }
        }

        float mx0 = -1e30f, mx1 = -1e30f;
#pragma unroll
        for (int n = 0; n < 8; n++) {
            mx0 = fmaxf(mx0, fmaxf(cs[n][0], cs[n][1]));
            mx1 = fmaxf(mx1, fmaxf(cs[n][2], cs[n][3]));
        }
        mx0 = fmaxf(mx0, __shfl_xor_sync(0xffffffffu, mx0, 1));
        mx0 = fmaxf(mx0, __shfl_xor_sync(0xffffffffu, mx0, 2));
        mx1 = fmaxf(mx1, __shfl_xor_sync(0xffffffffu, mx1, 1));
        mx1 = fmaxf(mx1, __shfl_xor_sync(0xffffffffu, mx1, 2));
        float nm0 = fmaxf(m0, mx0);
        float nm1 = fmaxf(m1, mx1);
        float f0 = ex2f(m0 - nm0);
        float f1 = ex2f(m1 - nm1);
        m0 = nm0; m1 = nm1;

        uint32_t pp[8][2];
#pragma unroll
        for (int n = 0; n < 8; n++) {
            pp[n][0] = ex2_f16x2(pack_f16x2(cs[n][0] - nm0, cs[n][1] - nm0));
            pp[n][1] = ex2_f16x2(pack_f16x2(cs[n][2] - nm1, cs[n][3] - nm1));
        }

#pragma unroll
        for (int n = 0; n < 8; n++) {
            co[n][0] *= f0; co[n][1] *= f0;
            co[n][2] *= f1; co[n][3] *= f1;
        }
        lacc[0] *= f0; lacc[2] *= f1;

#pragma unroll
        for (int kk = 0; kk < 4; kk++) {
            uint32_t pa[4] = {pp[2 * kk][0], pp[2 * kk][1],
                              pp[2 * kk + 1][0], pp[2 * kk + 1][1]};
#pragma unroll
            for (int ng = 0; ng < 4; ng++) {
                uint32_t vaddr = (uint32_t)((kk * 16 + (lane & 15)) * FSTRB
                                            + (ng * 16 + (lane >> 4) * 8) * 2);
                uint32_t vf[4];
                ldsm4t(vf, sVf + vaddr);
                mma16816h(co[ng * 2], pa, vf);
                mma16816h(co[ng * 2 + 1], pa, vf + 2);
            }
            uint32_t v1[2];
            ldsm2t(v1, sVf + (uint32_t)((kk * 16 + (lane & 15)) * FSTRB + 128));
            mma16816h(lacc, pa, v1);
        }

        __syncthreads();
        if (kt + 2 < nkt) LOADKV(kt + 2);
    }

    float l0 = __shfl_sync(0xffffffffu, lacc[0], lane & ~3);
    float l1 = __shfl_sync(0xffffffffu, lacc[2], lane & ~3);
    float inv0 = 1.0f / l0;
    float inv1 = 1.0f / l1;

    int srow = qb * 128 + wm * 16 + (lane >> 2);
    size_t base0 = ((size_t)(b * SS) + srow) * QDIM + h * 64 + (lane & 3) * 2;
    size_t base1 = base0 + (size_t)8 * QDIM;
#pragma unroll
    for (int nd = 0; nd < 8; nd++) {
        *(__half2*)(Of + base0 + nd * 8) =
            __floats2half2_rn(co[nd][0] * inv0, co[nd][1] * inv0);
        *(__half2*)(Of + base1 + nd * 8) =
            __floats2half2_rn(co[nd][2] * inv1, co[nd][3] * inv1);
    }
#undef LOADKV
}

// ---------------------------------------------------------------------------
// Launch: cvt_all, gemmQKV(fused rope), flash, gemmO  (4 launches)
// ---------------------------------------------------------------------------
extern "C" void kernel_launch(void* const* d_in, const int* in_sizes, int n_in,
                              void* d_out, int out_size) {
    const float* x = (const float*)d_in[0];
    const float* wq = (const float*)d_in[1];
    const float* wk = (const float*)d_in[2];
    const float* wv = (const float*)d_in[3];
    const float* wo = (const float*)d_in[4];
    const float* cosT = (const float*)d_in[5];
    const float* sinT = (const float*)d_in[6];
    float* out = (float*)d_out;

    __half *xf, *Wc, *Wof, *Qf, *Kf, *Vf, *Of;
    cudaGetSymbolAddress((void**)&xf, g_xf);
    cudaGetSymbolAddress((void**)&Wc, g_Wc);
    cudaGetSymbolAddress((void**)&Wof, g_Wof);
    cudaGetSymbolAddress((void**)&Qf, g_Qf);
    cudaGetSymbolAddress((void**)&Kf, g_Kf);
    cudaGetSymbolAddress((void**)&Vf, g_Vf);
    cudaGetSymbolAddress((void**)&Of, g_Of);

    cudaFuncSetAttribute(gemm2<0>, cudaFuncAttributeMaxDynamicSharedMemorySize,
                         G_SMEM_TOTAL);
    cudaFuncSetAttribute(gemm2<1>, cudaFuncAttributeMaxDynamicSharedMemorySize,
                         G_SMEM_TOTAL);
    cudaFuncSetAttribute(flash_mma, cudaFuncAttributeMaxDynamicSharedMemorySize,
                         FL_SMEM);

    // 1. All input conversions (plain fp16)
    cvt_all<<<(CV_TOTAL + 255) / 256, 256>>>(x, wq, wk, wv, wo, xf, Wc, Wof);

    // 2. Fused QKV projection + RoPE + relayout (512-thread CTAs)
    gemm2<1><<<dim3(QKVD / 128, MTOT / 256), 512, G_SMEM_TOTAL>>>(
        xf, Wc, nullptr, QKVD, DM, cosT, sinT, Qf, Kf, Vf);

    // 3. Attention (writes fp16 O)
    flash_mma<<<dim3(SS / 128, NH, BB), 256, FL_SMEM>>>(Qf, Kf, Vf, Of);

    // 4. Output projection: out = Of @ Wof^T (512-thread CTAs)
    gemm2<0><<<dim3(DM / 128, MTOT / 256), 512, G_SMEM_TOTAL>>>(
        Of, Wof, out, DM, QDIM, nullptr, nullptr, nullptr, nullptr, nullptr);
}

// round 17
// speedup vs baseline: 1.1186x; 1.1186x over previous
#include <cuda_runtime.h>
#include <cuda_bf16.h>
#include <cuda_fp16.h>
#include <math.h>
#include <stdint.h>

// Problem constants
#define BB 2
#define SS 2048
#define DM 2048
#define NH 32
#define NKV 8
#define HD 64
#define MTOT (BB * SS)          // 4096
#define QDIM (NH * HD)          // 2048
#define KVDIM (NKV * HD)        // 512
#define QKVD (QDIM + 2 * KVDIM) // 3072

// scale/log2 fold: (1/sqrt(64)) * log2(e)
#define QSCALE 0.18033688011112042f

// ---------------------------------------------------------------------------
// Scratch (device globals)
// ---------------------------------------------------------------------------
__device__ __half g_xf[MTOT * DM];              // x fp16
__device__ __half g_Wc[QKVD * DM];              // [wq;wk;wv] fp16
__device__ __half g_Wof[DM * QDIM];             // wo fp16
// per-head attention operands [b][h][s][64]
__device__ __half g_Qf[BB * NH * SS * HD];      // fp16, QSCALE folded
__device__ __half g_Kf[BB * NKV * SS * HD];     // fp16
__device__ __half g_Vf[BB * NKV * SS * HD];     // fp16
// attention output fp16, [b][s][2048] (GEMM-ready)
__device__ __half g_Of[MTOT * QDIM];

// ---------------------------------------------------------------------------
// PTX helpers
// ---------------------------------------------------------------------------
__device__ __forceinline__ uint32_t smem_u32(const void* p) {
    uint32_t a;
    asm("{ .reg .u64 t; cvta.to.shared.u64 t, %1; cvt.u32.u64 %0, t; }" : "=r"(a) : "l"(p));
    return a;
}
__device__ __forceinline__ void ldsm4(uint32_t* r, uint32_t addr) {
    asm volatile("ldmatrix.sync.aligned.m8n8.x4.shared.b16 {%0,%1,%2,%3}, [%4];"
                 : "=r"(r[0]), "=r"(r[1]), "=r"(r[2]), "=r"(r[3]) : "r"(addr));
}
__device__ __forceinline__ void ldsm4t(uint32_t* r, uint32_t addr) {
    asm volatile("ldmatrix.sync.aligned.m8n8.x4.trans.shared.b16 {%0,%1,%2,%3}, [%4];"
                 : "=r"(r[0]), "=r"(r[1]), "=r"(r[2]), "=r"(r[3]) : "r"(addr));
}
__device__ __forceinline__ void ldsm2t(uint32_t* r, uint32_t addr) {
    asm volatile("ldmatrix.sync.aligned.m8n8.x2.trans.shared.b16 {%0,%1}, [%2];"
                 : "=r"(r[0]), "=r"(r[1]) : "r"(addr));
}
__device__ __forceinline__ void mma16816h(float* c, const uint32_t* a, const uint32_t* b) {
    asm volatile(
        "mma.sync.aligned.m16n8k16.row.col.f32.f16.f16.f32 "
        "{%0,%1,%2,%3}, {%4,%5,%6,%7}, {%8,%9}, {%0,%1,%2,%3};"
        : "+f"(c[0]), "+f"(c[1]), "+f"(c[2]), "+f"(c[3])
        : "r"(a[0]), "r"(a[1]), "r"(a[2]), "r"(a[3]), "r"(b[0]), "r"(b[1]));
}
__device__ __forceinline__ void cp_async16(uint32_t saddr, const void* gaddr) {
    asm volatile("cp.async.cg.shared.global [%0], [%1], 16;" :: "r"(saddr), "l"(gaddr));
}
__device__ __forceinline__ float ex2f(float x) {
    float y;
    asm("ex2.approx.ftz.f32 %0, %1;" : "=f"(y) : "f"(x));
    return y;
}
__device__ __forceinline__ uint32_t pack_f16x2(float lo, float hi) {
    uint32_t d;
    asm("cvt.rn.f16x2.f32 %0, %1, %2;" : "=r"(d) : "f"(hi), "f"(lo));
    return d;
}
__device__ __forceinline__ uint32_t ex2_f16x2(uint32_t x) {
    uint32_t y;
    asm("ex2.approx.f16x2 %0, %1;" : "=r"(y) : "r"(x));
    return y;
}

// ---------------------------------------------------------------------------
// fp16 1-term GEMM: C = A[M,K] * B[NN,K]^T  (fp32 acc)
// CTA 256x128, BK=64, 256 threads (8 warps 4m x 2n, warp 64x64), 2-stage
// cp.async. Row stride 144B (conflict-free, flash-validated).
// MODE 0: fp32 C.  MODE 1 (QKV): fused RoPE + fp16 + per-head relayout.
// ---------------------------------------------------------------------------
#define GA_ARR (256 * 144)             // 36864
#define GB_ARR (128 * 144)             // 18432
#define G_STAGE (GA_ARR + GB_ARR)      // 55296
#define G_SMEM_TOTAL (2 * G_STAGE)     // 110592

template <int MODE>
__global__ __launch_bounds__(256, 1) void gemm2(
    const __half* __restrict__ A, const __half* __restrict__ B,
    float* __restrict__ C, int NN, int K,
    const float* __restrict__ cosT, const float* __restrict__ sinT,
    __half* __restrict__ Qf, __half* __restrict__ Kf, __half* __restrict__ Vf)
{
    extern __shared__ char smem[];
    const uint32_t sb = smem_u32(smem);
    const int tid = threadIdx.x;
    const int wid = tid >> 5;
    const int lane = tid & 31;
    const int wm = wid & 3;
    const int wn = wid >> 2;
    const int m0 = blockIdx.y * 256;
    const int n0 = blockIdx.x * 128;

    const __half* const Ap = A + (size_t)m0 * K;
    const __half* const Bp = B + (size_t)n0 * K;

    float acc[4][8][4];
#pragma unroll
    for (int i = 0; i < 4; i++)
#pragma unroll
        for (int j = 0; j < 8; j++)
#pragma unroll
            for (int q = 0; q < 4; q++) acc[i][j][q] = 0.0f;

    const int NC = K / 64;
    const int lg = lane >> 3;
    const int lr = lane & 7;

#define LOADSTAGE(cc) do {                                                     \
    const uint32_t stg = ((cc) & 1) ? G_STAGE : 0;                             \
    const int k0 = (cc) * 64;                                                  \
    _Pragma("unroll")                                                          \
    for (int i = 0; i < 12; i++) {                                             \
        int gidx = tid + i * 256;       /* 0..3071 */                          \
        if (gidx < 2048) {              /* A: 256 rows x 8 chunks */           \
            int row = gidx >> 3;                                               \
            int q = gidx & 7;                                                  \
            cp_async16(sb + stg + row * 144 + q * 16,                          \
                       Ap + (size_t)row * K + k0 + q * 8);                     \
        } else {                        /* B: 128 rows x 8 chunks */           \
            int w = gidx - 2048;                                               \
            int row = w >> 3;                                                  \
            int q = w & 7;                                                     \
            cp_async16(sb + stg + GA_ARR + row * 144 + q * 16,                 \
                       Bp + (size_t)row * K + k0 + q * 8);                     \
        }                                                                      \
    }                                                                          \
    asm volatile("cp.async.commit_group;" ::: "memory");                       \
} while (0)

    LOADSTAGE(0);

    for (int c = 0; c < NC; c++) {
        asm volatile("cp.async.wait_group 0;" ::: "memory");
        __syncthreads();
        if (c + 1 < NC) LOADSTAGE(c + 1);

        const uint32_t stg = sb + ((c & 1) ? G_STAGE : 0);
        const uint32_t sA = stg;
        const uint32_t sB = stg + GA_ARR;

#pragma unroll
        for (int kk = 0; kk < 4; kk++) {
            const int kbyte = kk * 32;
            uint32_t fA[4][4];
#pragma unroll
            for (int mt = 0; mt < 4; mt++) {
                int arow = wm * 64 + mt * 16 + (lg & 1) * 8 + lr;
                uint32_t aoff = (uint32_t)(arow * 144 + kbyte + (lg >> 1) * 16);
                ldsm4(fA[mt], sA + aoff);
            }
#pragma unroll
            for (int np = 0; np < 4; np++) {
                int brow = wn * 64 + np * 16 + (lg >> 1) * 8 + lr;
                uint32_t boff = (uint32_t)(brow * 144 + kbyte + (lg & 1) * 16);
                uint32_t fB[4];
                ldsm4(fB, sB + boff);
#pragma unroll
                for (int mt = 0; mt < 4; mt++) {
                    mma16816h(acc[mt][np * 2], fA[mt], fB);
                    mma16816h(acc[mt][np * 2 + 1], fA[mt], fB + 2);
                }
            }
        }
        __syncthreads();
    }

    if (MODE == 0) {
#pragma unroll
        for (int mt = 0; mt < 4; mt++) {
            int row0 = m0 + wm * 64 + mt * 16 + (lane >> 2);
#pragma unroll
            for (int nt = 0; nt < 8; nt++) {
                int col = n0 + wn * 64 + nt * 8 + (lane & 3) * 2;
                float2 v0 = {acc[mt][nt][0], acc[mt][nt][1]};
                float2 v1 = {acc[mt][nt][2], acc[mt][nt][3]};
                *(float2*)(C + (size_t)row0 * NN + col) = v0;
                *(float2*)(C + (size_t)(row0 + 8) * NN + col) = v1;
            }
        }
    } else {
        // Fused QKV epilogue. Warp's 64-col tile = exactly one head.
        const int col0 = n0 + wn * 64;
#pragma unroll
        for (int mt = 0; mt < 4; mt++) {
#pragma unroll
            for (int rr = 0; rr < 2; rr++) {
                int row = m0 + wm * 64 + mt * 16 + (lane >> 2) + rr * 8;
                int s = row & (SS - 1);
                int b = row >> 11;
                if (col0 < QDIM + KVDIM) {
                    bool isQ = col0 < QDIM;
                    __half* dst;
                    if (isQ) {
                        int h = col0 >> 6;
                        dst = Qf + ((size_t)(b * NH + h) * SS + s) * 64;
                    } else {
                        int kvh = (col0 - QDIM) >> 6;
                        dst = Kf + ((size_t)(b * NKV + kvh) * SS + s) * 64;
                    }
                    float sc = isQ ? QSCALE : 1.0f;
#pragma unroll
                    for (int nt = 0; nt < 4; nt++) {
                        int d = nt * 8 + (lane & 3) * 2;
                        float a0 = acc[mt][nt][rr * 2], a1 = acc[mt][nt][rr * 2 + 1];
                        float b0 = acc[mt][nt + 4][rr * 2], b1 = acc[mt][nt + 4][rr * 2 + 1];
                        int ci = s * 32 + (d >> 1);
                        float c1 = cosT[ci], s1 = sinT[ci];
                        float c2 = cosT[ci + 16], s2 = sinT[ci + 16];
                        __half2 lo2 = __floats2half2_rn((a0 * c1 - b0 * s1) * sc,
                                                        (a1 * c1 - b1 * s1) * sc);
                        __half2 hi2 = __floats2half2_rn((b0 * c2 + a0 * s2) * sc,
                                                        (b1 * c2 + a1 * s2) * sc);
                        *(__half2*)(dst + d) = lo2;
                        *(__half2*)(dst + d + 32) = hi2;
                    }
                } else {
                    int kvh = (col0 - QDIM - KVDIM) >> 6;
                    __half* dst = Vf + ((size_t)(b * NKV + kvh) * SS + s) * 64;
#pragma unroll
                    for (int nt = 0; nt < 8; nt++) {
                        int d = nt * 8 + (lane & 3) * 2;
                        *(__half2*)(dst + d) =
                            __floats2half2_rn(acc[mt][nt][rr * 2], acc[mt][nt][rr * 2 + 1]);
                    }
                }
            }
        }
    }
#undef LOADSTAGE
}

// ---------------------------------------------------------------------------
// cvt_all: x, [wq;wk;wv], wo -> fp16
// ---------------------------------------------------------------------------
#define CV_NX (MTOT * DM / 2)
#define CV_NQ (QDIM * DM / 2)
#define CV_NK (KVDIM * DM / 2)
#define CV_NO (DM * QDIM / 2)
#define CV_TOTAL (CV_NX + CV_NQ + 2 * CV_NK + CV_NO)

__global__ void cvt_all(const float* __restrict__ x, const float* __restrict__ wq,
                        const float* __restrict__ wk, const float* __restrict__ wv,
                        const float* __restrict__ wo,
                        __half* __restrict__ xf, __half* __restrict__ Wc,
                        __half* __restrict__ Wof) {
    int i = blockIdx.x * blockDim.x + threadIdx.x;
    const float* src;
    __half* dst;
    int off;
    if (i < CV_NX) { src = x; dst = xf; off = i; }
    else if (i < CV_NX + CV_NQ) { src = wq; dst = Wc; off = i - CV_NX; }
    else if (i < CV_NX + CV_NQ + CV_NK) {
        src = wk; dst = Wc + (size_t)QDIM * DM; off = i - CV_NX - CV_NQ;
    } else if (i < CV_NX + CV_NQ + 2 * CV_NK) {
        src = wv; dst = Wc + (size_t)(QDIM + KVDIM) * DM; off = i - CV_NX - CV_NQ - CV_NK;
    } else if (i < CV_TOTAL) {
        src = wo; dst = Wof; off = i - CV_NX - CV_NQ - 2 * CV_NK;
    } else return;
    float2 v = ((const float2*)src)[off];
    ((__half2*)dst)[off] = __floats2half2_rn(v.x, v.y);
}

// ---------------------------------------------------------------------------
// MMA flash attention v5: fp16 QxK (1 MMA), fp16 PxV (1 MMA), ones-column
// row sums. KV tile 128 (softmax fixed costs halved). LPT order.
// grid (S/128, NH, BB), 256 threads.
// ---------------------------------------------------------------------------
#define FSTRB 144
#define FQ_BYTES (128 * FSTRB)       // 18432
#define FARR (128 * FSTRB)           // 18432 (128-row K or V tile)
#define FKV0 FQ_BYTES
#define FSTAGE (2 * FARR)            // 36864
#define FL_SMEM (FKV0 + 2 * FSTAGE)  // 92160

__global__ __launch_bounds__(256, 1) void flash_mma(
    const __half* __restrict__ Qf, const __half* __restrict__ Kf,
    const __half* __restrict__ Vf, __half* __restrict__ Of)
{
    extern __shared__ char sm[];
    const uint32_t sb = smem_u32(sm);
    const int tid = threadIdx.x;
    const int lane = tid & 31;
    const int wm = tid >> 5;
    const int qb = (gridDim.x - 1) - blockIdx.x;   // LPT: big tiles first
    const int h = blockIdx.y;
    const int b = blockIdx.z;
    const int kvh = h >> 2;
    const int nkt = qb + 1;                        // 128-wide KV tiles

    const size_t qg = ((size_t)(b * NH + h) * SS + qb * 128) * 64;
    const size_t kg = ((size_t)(b * NKV + kvh) * SS) * 64;

    {
#pragma unroll
        for (int i = 0; i < 4; i++) {
            int g = tid + i * 256;
            int row = g >> 3;
            int ch = g & 7;
            cp_async16(sb + row * FSTRB + ch * 16, Qf + qg + (size_t)row * 64 + ch * 8);
        }
        asm volatile("cp.async.commit_group;" ::: "memory");
    }

#define LOADKV(kt_) do {                                                        \
    int j0_ = (kt_) * 128;                                                      \
    uint32_t stg_ = sb + FKV0 + ((kt_) & 1) * FSTAGE;                           \
    const char* karr[2] = {                                                     \
        (const char*)(Kf + kg + (size_t)j0_ * 64),                              \
        (const char*)(Vf + kg + (size_t)j0_ * 64)};                             \
    _Pragma("unroll")                                                           \
    for (int i = 0; i < 8; i++) {                                               \
        int g = tid + i * 256;          /* 0..2047 */                           \
        int arr = g >> 10;                                                      \
        int w = g & 1023;                                                       \
        int row = w >> 3;                                                       \
        int ch = w & 7;                                                         \
        cp_async16(stg_ + arr * FARR + row * FSTRB + ch * 16,                   \
                   karr[arr] + row * 128 + ch * 16);                            \
    }                                                                           \
    asm volatile("cp.async.commit_group;" ::: "memory");                        \
} while (0)

    LOADKV(0);
    if (nkt > 1) LOADKV(1);

    // V pad init: ones column (col 64 = 1.0h), both stages, 128 rows each.
    if (tid < 256) {
        int stage = tid >> 7;
        int row = tid & 127;
        uint32_t off = FKV0 + stage * FSTAGE + FARR + row * FSTRB + 128;
        uint4 ones = {0x00003C00u, 0u, 0u, 0u};
        *(uint4*)(sm + off) = ones;
    }

    if (nkt > 1) { asm volatile("cp.async.wait_group 1;" ::: "memory"); }
    else         { asm volatile("cp.async.wait_group 0;" ::: "memory"); }
    __syncthreads();

    uint32_t qf[4][4];
#pragma unroll
    for (int kk = 0; kk < 4; kk++) {
        uint32_t addr = sb + (uint32_t)((wm * 16 + (lane & 15)) * FSTRB
                                        + kk * 32 + (lane >> 4) * 16);
        ldsm4(qf[kk], addr);
    }

    float co[8][4];
#pragma unroll
    for (int i = 0; i < 8; i++)
#pragma unroll
        for (int j = 0; j < 4; j++) co[i][j] = 0.0f;
    float lacc[4] = {0.0f, 0.0f, 0.0f, 0.0f};
    float m0 = -1e30f, m1 = -1e30f;

    const int lg = lane >> 3;
    const int lr = lane & 7;
    const int qr0 = qb * 128 + wm * 16 + (lane >> 2);

    for (int kt = 0; kt < nkt; kt++) {
        if (kt > 0) {
            if (kt + 1 < nkt) { asm volatile("cp.async.wait_group 1;" ::: "memory"); }
            else              { asm volatile("cp.async.wait_group 0;" ::: "memory"); }
            __syncthreads();
        }
        const uint32_t sKf = sb + FKV0 + (kt & 1) * FSTAGE;
        const uint32_t sVf = sKf + FARR;

        // ---- S = Qf Kf^T over 128 keys (16 n8 tiles) ----
        float cs[16][4];
#pragma unroll
        for (int i = 0; i < 16; i++)
#pragma unroll
            for (int j = 0; j < 4; j++) cs[i][j] = 0.0f;

#pragma unroll
        for (int kk = 0; kk < 4; kk++) {
#pragma unroll
            for (int ng = 0; ng < 8; ng++) {
                uint32_t boff = (uint32_t)((ng * 16 + (lg >> 1) * 8 + lr) * FSTRB
                                           + kk * 32 + (lg & 1) * 16);
                uint32_t bk[4];
                ldsm4(bk, sKf + boff);
                mma16816h(cs[ng * 2], qf[kk], bk);
                mma16816h(cs[ng * 2 + 1], qf[kk], bk + 2);
            }
        }

        // ---- causal mask (final tile only) ----
        if (kt == nkt - 1) {
            int gcol0 = kt * 128 + (lane & 3) * 2;
#pragma unroll
            for (int n = 0; n < 16; n++) {
#pragma unroll
                for (int t = 0; t < 2; t++) {
                    int col = gcol0 + n * 8 + t;
                    if (col > qr0) cs[n][t] = -1e30f;
                    if (col > qr0 + 8) cs[n][t + 2] = -1e30f;
                }
            }
        }

        // ---- online softmax (base-2) once per 128 keys ----
        float mx0 = -1e30f, mx1 = -1e30f;
#pragma unroll
        for (int n = 0; n < 16; n++) {
            mx0 = fmaxf(mx0, fmaxf(cs[n][0], cs[n][1]));
            mx1 = fmaxf(mx1, fmaxf(cs[n][2], cs[n][3]));
        }
        mx0 = fmaxf(mx0, __shfl_xor_sync(0xffffffffu, mx0, 1));
        mx0 = fmaxf(mx0, __shfl_xor_sync(0xffffffffu, mx0, 2));
        mx1 = fmaxf(mx1, __shfl_xor_sync(0xffffffffu, mx1, 1));
        mx1 = fmaxf(mx1, __shfl_xor_sync(0xffffffffu, mx1, 2));
        float nm0 = fmaxf(m0, mx0);
        float nm1 = fmaxf(m1, mx1);
        float f0 = ex2f(m0 - nm0);
        float f1 = ex2f(m1 - nm1);
        m0 = nm0; m1 = nm1;

        uint32_t pp[16][2];
#pragma unroll
        for (int n = 0; n < 16; n++) {
            pp[n][0] = ex2_f16x2(pack_f16x2(cs[n][0] - nm0, cs[n][1] - nm0));
            pp[n][1] = ex2_f16x2(pack_f16x2(cs[n][2] - nm1, cs[n][3] - nm1));
        }

#pragma unroll
        for (int n = 0; n < 8; n++) {
            co[n][0] *= f0; co[n][1] *= f0;
            co[n][2] *= f1; co[n][3] *= f1;
        }
        lacc[0] *= f0; lacc[2] *= f1;

        // ---- O += P V (8 k16 groups over 128 keys) + ones-column sums ----
#pragma unroll
        for (int kk = 0; kk < 8; kk++) {
            uint32_t pa[4] = {pp[2 * kk][0], pp[2 * kk][1],
                              pp[2 * kk + 1][0], pp[2 * kk + 1][1]};
#pragma unroll
            for (int ng = 0; ng < 4; ng++) {
                uint32_t vaddr = (uint32_t)((kk * 16 + (lane & 15)) * FSTRB
                                            + (ng * 16 + (lane >> 4) * 8) * 2);
                uint32_t vf[4];
                ldsm4t(vf, sVf + vaddr);
                mma16816h(co[ng * 2], pa, vf);
                mma16816h(co[ng * 2 + 1], pa, vf + 2);
            }
            uint32_t v1[2];
            ldsm2t(v1, sVf + (uint32_t)((kk * 16 + (lane & 15)) * FSTRB + 128));
            mma16816h(lacc, pa, v1);
        }

        __syncthreads();
        if (kt + 2 < nkt) LOADKV(kt + 2);
    }

    float l0 = __shfl_sync(0xffffffffu, lacc[0], lane & ~3);
    float l1 = __shfl_sync(0xffffffffu, lacc[2], lane & ~3);
    float inv0 = 1.0f / l0;
    float inv1 = 1.0f / l1;

    int srow = qb * 128 + wm * 16 + (lane >> 2);
    size_t base0 = ((size_t)(b * SS) + srow) * QDIM + h * 64 + (lane & 3) * 2;
    size_t base1 = base0 + (size_t)8 * QDIM;
#pragma unroll
    for (int nd = 0; nd < 8; nd++) {
        *(__half2*)(Of + base0 + nd * 8) =
            __floats2half2_rn(co[nd][0] * inv0, co[nd][1] * inv0);
        *(__half2*)(Of + base1 + nd * 8) =
            __floats2half2_rn(co[nd][2] * inv1, co[nd][3] * inv1);
    }
#undef LOADKV
}

// ---------------------------------------------------------------------------
// Launch: cvt_all, gemmQKV(fused rope), flash, gemmO  (4 launches)
// ---------------------------------------------------------------------------
extern "C" void kernel_launch(void* const* d_in, const int* in_sizes, int n_in,
                              void* d_out, int out_size) {
    const float* x = (const float*)d_in[0];
    const float* wq = (const float*)d_in[1];
    const float* wk = (const float*)d_in[2];
    const float* wv = (const float*)d_in[3];
    const float* wo = (const float*)d_in[4];
    const float* cosT = (const float*)d_in[5];
    const float* sinT = (const float*)d_in[6];
    float* out = (float*)d_out;

    __half *xf, *Wc, *Wof, *Qf, *Kf, *Vf, *Of;
    cudaGetSymbolAddress((void**)&xf, g_xf);
    cudaGetSymbolAddress((void**)&Wc, g_Wc);
    cudaGetSymbolAddress((void**)&Wof, g_Wof);
    cudaGetSymbolAddress((void**)&Qf, g_Qf);
    cudaGetSymbolAddress((void**)&Kf, g_Kf);
    cudaGetSymbolAddress((void**)&Vf, g_Vf);
    cudaGetSymbolAddress((void**)&Of, g_Of);

    cudaFuncSetAttribute(gemm2<0>, cudaFuncAttributeMaxDynamicSharedMemorySize,
                         G_SMEM_TOTAL);
    cudaFuncSetAttribute(gemm2<1>, cudaFuncAttributeMaxDynamicSharedMemorySize,
                         G_SMEM_TOTAL);
    cudaFuncSetAttribute(flash_mma, cudaFuncAttributeMaxDynamicSharedMemorySize,
                         FL_SMEM);

    // 1. All input conversions (plain fp16)
    cvt_all<<<(CV_TOTAL + 255) / 256, 256>>>(x, wq, wk, wv, wo, xf, Wc, Wof);

    // 2. Fused QKV projection + RoPE + relayout
    gemm2<1><<<dim3(QKVD / 128, MTOT / 256), 256, G_SMEM_TOTAL>>>(
        xf, Wc, nullptr, QKVD, DM, cosT, sinT, Qf, Kf, Vf);

    // 3. Attention (writes fp16 O)
    flash_mma<<<dim3(SS / 128, NH, BB), 256, FL_SMEM>>>(Qf, Kf, Vf, Of);

    // 4. Output projection: out = Of @ Wof^T
    gemm2<0><<<dim3(DM / 128, MTOT / 256), 256, G_SMEM_TOTAL>>>(
        Of, Wof, out, DM, QDIM, nullptr, nullptr, nullptr, nullptr, nullptr);
}